// round 1
// baseline (speedup 1.0000x reference)
#include <cuda_runtime.h>

#define N_NODES 10000
#define N_EDGES 320000
#define ETOT    330000   // edges + self loops
#define H       128
#define F_IN    256
#define NEG_SLOPE 0.2f

// ---------------- scratch (device globals; no allocations allowed) ----------
__device__ float g_h [N_NODES * H];   // GEMM output (pre-aggregation h)
__device__ float g_hn[N_NODES * H];   // post-GAT relu output (layer input)
__device__ float g_as[N_NODES];
__device__ float g_ad[N_NODES];
__device__ float g_exp[ETOT];         // exp(leaky(e)) in CSR-permuted order
__device__ int   g_cnt[N_NODES];
__device__ int   g_off[N_NODES + 1];
__device__ int   g_cur[N_NODES];
__device__ int   g_psrc[ETOT];        // src node per CSR slot
__device__ int   g_pos[ETOT];         // original edge -> CSR slot
__device__ float g_acc2[2];

// ---------------- init ------------------------------------------------------
__global__ void k_init() {
    int i = blockIdx.x * blockDim.x + threadIdx.x;
    if (i < N_NODES) g_cnt[i] = 0;
    if (i < 2) g_acc2[i] = 0.0f;
}

// ---------------- CSR build: histogram, scan, scatter ------------------------
__device__ __forceinline__ void edge_sd(const int* ei, int i, int& s, int& d) {
    if (i < N_EDGES) { s = ei[i]; d = ei[N_EDGES + i]; }
    else             { s = i - N_EDGES; d = s; }          // self loops
}

__global__ void k_hist(const int* __restrict__ ei) {
    int i = blockIdx.x * blockDim.x + threadIdx.x;
    if (i >= ETOT) return;
    int s, d; edge_sd(ei, i, s, d);
    atomicAdd(&g_cnt[d], 1);
}

__global__ void k_scan() {   // single block, 1024 threads
    __shared__ int sd[1024];
    const int CH = (N_NODES + 1023) / 1024;   // 10
    int t = threadIdx.x;
    int base = t * CH;
    int local[CH];
    int sum = 0;
    #pragma unroll
    for (int k = 0; k < CH; k++) {
        int i = base + k;
        int c = (i < N_NODES) ? g_cnt[i] : 0;
        local[k] = sum;
        sum += c;
    }
    sd[t] = sum;
    __syncthreads();
    for (int o = 1; o < 1024; o <<= 1) {
        int v = (t >= o) ? sd[t - o] : 0;
        __syncthreads();
        sd[t] += v;
        __syncthreads();
    }
    int excl = sd[t] - sum;
    #pragma unroll
    for (int k = 0; k < CH; k++) {
        int i = base + k;
        if (i < N_NODES) {
            int o = excl + local[k];
            g_off[i] = o;
            g_cur[i] = o;
        }
    }
    if (t == 0) g_off[N_NODES] = ETOT;
}

__global__ void k_scatter(const int* __restrict__ ei) {
    int i = blockIdx.x * blockDim.x + threadIdx.x;
    if (i >= ETOT) return;
    int s, d; edge_sd(ei, i, s, d);
    int p = atomicAdd(&g_cur[d], 1);
    g_psrc[p] = s;
    g_pos[i] = p;
}

// ---------------- GEMM: g_h[M,128] = A[M,K] @ B[K,128] ----------------------
// BM=64, BN=128 (full width), BK=16, 256 threads, 8x4 per-thread tile.
#define BM 64
#define BN 128
#define BK 16
__global__ void k_gemm(const float* __restrict__ Ain,
                       const float* __restrict__ B, int M, int K) {
    const float* A = Ain ? Ain : g_hn;   // layer 2 reads relu(h1)
    __shared__ float As[BK][BM];
    __shared__ float Bs[BK][BN];

    int tid = threadIdx.x;
    int tn  = tid & 31;   // 32 col groups * 4 cols
    int tm  = tid >> 5;   // 8 row groups * 8 rows
    int m0  = blockIdx.x * BM;

    float acc[8][4];
    #pragma unroll
    for (int i = 0; i < 8; i++)
        #pragma unroll
        for (int j = 0; j < 4; j++) acc[i][j] = 0.0f;

    int a_row = tid >> 2;          // 0..63
    int a_col = (tid & 3) * 4;     // 0,4,8,12

    for (int k0 = 0; k0 < K; k0 += BK) {
        // A tile (64x16), float4 per thread, store transposed
        int gm = m0 + a_row;
        float4 av = (gm < M) ? *(const float4*)(A + (size_t)gm * K + k0 + a_col)
                             : make_float4(0.f, 0.f, 0.f, 0.f);
        As[a_col + 0][a_row] = av.x;
        As[a_col + 1][a_row] = av.y;
        As[a_col + 2][a_row] = av.z;
        As[a_col + 3][a_row] = av.w;
        // B tile (16x128), 2 float4 per thread
        #pragma unroll
        for (int t = 0; t < 2; t++) {
            int q   = tid * 2 + t;       // 0..511
            int brr = q >> 5;            // row 0..15
            int bcc = (q & 31) * 4;      // col
            *(float4*)&Bs[brr][bcc] = *(const float4*)(B + (size_t)(k0 + brr) * BN + bcc);
        }
        __syncthreads();

        #pragma unroll
        for (int kk = 0; kk < BK; kk++) {
            float4 a0 = *(const float4*)&As[kk][tm * 8];
            float4 a1 = *(const float4*)&As[kk][tm * 8 + 4];
            float4 b  = *(const float4*)&Bs[kk][tn * 4];
            float a[8] = {a0.x, a0.y, a0.z, a0.w, a1.x, a1.y, a1.z, a1.w};
            #pragma unroll
            for (int i = 0; i < 8; i++) {
                acc[i][0] += a[i] * b.x;
                acc[i][1] += a[i] * b.y;
                acc[i][2] += a[i] * b.z;
                acc[i][3] += a[i] * b.w;
            }
        }
        __syncthreads();
    }
    #pragma unroll
    for (int i = 0; i < 8; i++) {
        int gm = m0 + tm * 8 + i;
        if (gm < M)
            *(float4*)(g_h + (size_t)gm * BN + tn * 4) =
                make_float4(acc[i][0], acc[i][1], acc[i][2], acc[i][3]);
    }
}

// ---------------- per-node attention scalars --------------------------------
__global__ void k_att(const float* __restrict__ att_s, const float* __restrict__ att_d) {
    int warp = (blockIdx.x * blockDim.x + threadIdx.x) >> 5;
    int lane = threadIdx.x & 31;
    if (warp >= N_NODES) return;
    float s = 0.f, d = 0.f;
    #pragma unroll
    for (int k = lane; k < H; k += 32) {
        float hv = g_h[(size_t)warp * H + k];
        s += hv * att_s[k];
        d += hv * att_d[k];
    }
    #pragma unroll
    for (int o = 16; o; o >>= 1) {
        s += __shfl_down_sync(0xffffffffu, s, o);
        d += __shfl_down_sync(0xffffffffu, d, o);
    }
    if (lane == 0) { g_as[warp] = s; g_ad[warp] = d; }
}

// ---------------- per-edge exp(leaky_relu(e)), written into CSR slots --------
// No segment-max needed: |e| <= ~5, exp stays tiny; exp(e-m)/sum == exp(e)/sum.
__global__ void k_edge(const int* __restrict__ ei) {
    int i = blockIdx.x * blockDim.x + threadIdx.x;
    if (i >= ETOT) return;
    int s, d; edge_sd(ei, i, s, d);
    float e = g_as[s] + g_ad[d];
    e = e > 0.f ? e : NEG_SLOPE * e;
    g_exp[g_pos[i]] = expf(e);
}

// ---------------- aggregation: one block per dst node, no atomics ------------
// out[d][j] = relu( (sum_e w_e * h[src_e][j]) / (sum_e w_e) + bias[j] )
__global__ void k_agg(const float* __restrict__ bias) {
    int d = blockIdx.x;
    int j = threadIdx.x;   // 0..127
    int s = g_off[d], e = g_off[d + 1];
    float acc = 0.f, z = 0.f;
    int p = s;
    for (; p + 2 <= e; p += 2) {
        int   s0 = __ldg(&g_psrc[p]),     s1 = __ldg(&g_psrc[p + 1]);
        float w0 = __ldg(&g_exp[p]),      w1 = __ldg(&g_exp[p + 1]);
        float h0 = g_h[(size_t)s0 * H + j];
        float h1 = g_h[(size_t)s1 * H + j];
        z   += w0 + w1;
        acc += w0 * h0 + w1 * h1;
    }
    if (p < e) {
        int s0 = __ldg(&g_psrc[p]);
        float w0 = __ldg(&g_exp[p]);
        z += w0;
        acc += w0 * g_h[(size_t)s0 * H + j];
    }
    float v = acc / z + bias[j];
    g_hn[(size_t)d * H + j] = fmaxf(v, 0.f);
}

// ---------------- tail: r = h2@Wr + br; out = r(1,N) @ Wc + bc ---------------
__global__ void k_reduce(const float* __restrict__ Wr, const float* __restrict__ br,
                         const float* __restrict__ Wc) {
    int gid    = blockIdx.x * blockDim.x + threadIdx.x;
    int warp   = gid >> 5;
    int lane   = threadIdx.x & 31;
    int nwarps = (gridDim.x * blockDim.x) >> 5;
    float s0 = 0.f, s1 = 0.f;
    for (int n = warp; n < N_NODES; n += nwarps) {
        float dot = 0.f;
        #pragma unroll
        for (int k = lane; k < H; k += 32)
            dot += g_hn[(size_t)n * H + k] * Wr[k];
        #pragma unroll
        for (int o = 16; o; o >>= 1) dot += __shfl_down_sync(0xffffffffu, dot, o);
        if (lane == 0) {
            float r = dot + br[0];
            s0 += r * Wc[n * 2 + 0];
            s1 += r * Wc[n * 2 + 1];
        }
    }
    if (lane == 0) {
        atomicAdd(&g_acc2[0], s0);
        atomicAdd(&g_acc2[1], s1);
    }
}

__global__ void k_fin(const float* __restrict__ bc, float* __restrict__ out) {
    int i = threadIdx.x;
    if (i < 2) out[i] = g_acc2[i] + bc[i];
}

// ---------------- launch -----------------------------------------------------
extern "C" void kernel_launch(void* const* d_in, const int* in_sizes, int n_in,
                              void* d_out, int out_size) {
    const float* x   = (const float*)d_in[0];
    const int*   ei  = (const int*)  d_in[1];
    const float* W1  = (const float*)d_in[2];
    const float* as1 = (const float*)d_in[3];
    const float* ad1 = (const float*)d_in[4];
    const float* b1  = (const float*)d_in[5];
    const float* W2  = (const float*)d_in[6];
    const float* as2 = (const float*)d_in[7];
    const float* ad2 = (const float*)d_in[8];
    const float* b2  = (const float*)d_in[9];
    const float* Wr  = (const float*)d_in[10];
    const float* br  = (const float*)d_in[11];
    const float* Wc  = (const float*)d_in[12];
    const float* bc  = (const float*)d_in[13];
    float* out = (float*)d_out;

    // CSR build (deterministic per input; rebuilt every call)
    k_init   <<<(N_NODES + 255) / 256, 256>>>();
    k_hist   <<<(ETOT + 255) / 256, 256>>>(ei);
    k_scan   <<<1, 1024>>>();
    k_scatter<<<(ETOT + 255) / 256, 256>>>(ei);

    int gemm_grid = (N_NODES + BM - 1) / BM;

    // ---- layer 1 ----
    k_gemm<<<gemm_grid, 256>>>(x, W1, N_NODES, F_IN);
    k_att <<<(N_NODES * 32 + 255) / 256, 256>>>(as1, ad1);
    k_edge<<<(ETOT + 255) / 256, 256>>>(ei);
    k_agg <<<N_NODES, H>>>(b1);

    // ---- layer 2 ----
    k_gemm<<<gemm_grid, 256>>>(nullptr, W2, N_NODES, H);
    k_att <<<(N_NODES * 32 + 255) / 256, 256>>>(as2, ad2);
    k_edge<<<(ETOT + 255) / 256, 256>>>(ei);
    k_agg <<<N_NODES, H>>>(b2);

    // ---- tail ----
    k_reduce<<<128, 256>>>(Wr, br, Wc);
    k_fin   <<<1, 32>>>(bc, out);
}

// round 2
// speedup vs baseline: 1.2772x; 1.2772x over previous
#include <cuda_runtime.h>

#define N_NODES 10000
#define N_EDGES 320000
#define ETOT    330000
#define H       128
#define F_IN    256
#define NEG_SLOPE 0.2f

// ---------------- scratch ----------------------------------------------------
__device__ float g_h  [N_NODES * H];   // GEMM output (pre-aggregation h)
__device__ float g_hn [N_NODES * H];   // post-GAT relu output (layer-2 input)
__device__ float g_as [N_NODES];
__device__ float g_ad [N_NODES];
__device__ int   g_cnt[N_NODES];
__device__ int   g_off[N_NODES + 1];
__device__ int   g_rank[ETOT];         // edge rank within its dst bucket
__device__ int   g_psrc[ETOT];         // src node per CSR slot
__device__ float g_acc2[2];

// ---------------- init -------------------------------------------------------
__global__ void k_init() {
    int i = blockIdx.x * blockDim.x + threadIdx.x;
    if (i < N_NODES) g_cnt[i] = 0;
    if (i < 2) g_acc2[i] = 0.0f;
}

__device__ __forceinline__ void edge_sd(const int* ei, int i, int& s, int& d) {
    if (i < N_EDGES) { s = ei[i]; d = ei[N_EDGES + i]; }
    else             { s = i - N_EDGES; d = s; }          // self loops
}

// histogram + per-edge rank in one pass
__global__ void k_hist(const int* __restrict__ ei) {
    int i = blockIdx.x * blockDim.x + threadIdx.x;
    if (i >= ETOT) return;
    int s, d; edge_sd(ei, i, s, d);
    g_rank[i] = atomicAdd(&g_cnt[d], 1);
}

__global__ void k_scan() {   // single block, 1024 threads
    __shared__ int sd[1024];
    const int CH = (N_NODES + 1023) / 1024;   // 10
    int t = threadIdx.x;
    int base = t * CH;
    int local[CH];
    int sum = 0;
    #pragma unroll
    for (int k = 0; k < CH; k++) {
        int i = base + k;
        int c = (i < N_NODES) ? g_cnt[i] : 0;
        local[k] = sum;
        sum += c;
    }
    sd[t] = sum;
    __syncthreads();
    for (int o = 1; o < 1024; o <<= 1) {
        int v = (t >= o) ? sd[t - o] : 0;
        __syncthreads();
        sd[t] += v;
        __syncthreads();
    }
    int excl = sd[t] - sum;
    #pragma unroll
    for (int k = 0; k < CH; k++) {
        int i = base + k;
        if (i < N_NODES) g_off[i] = excl + local[k];
    }
    if (t == 0) g_off[N_NODES] = ETOT;
}

// placement: no atomics, pure stores
__global__ void k_place(const int* __restrict__ ei) {
    int i = blockIdx.x * blockDim.x + threadIdx.x;
    if (i >= ETOT) return;
    int s, d; edge_sd(ei, i, s, d);
    g_psrc[g_off[d] + g_rank[i]] = s;
}

// ---------------- GEMM + fused attention dots --------------------------------
// g_h[M,128] = A[M,K] @ B[K,128]; also g_as[m]=h[m]·att_s, g_ad[m]=h[m]·att_d
// BM=64, BN=128, BK=16, 128 threads, 8x8 per-thread microtile (FMA-bound).
#define BM 64
#define BN 128
#define BK 16
__global__ __launch_bounds__(128, 2)
void k_gemm(const float* __restrict__ Ain, const float* __restrict__ B,
            const float* __restrict__ att_s, const float* __restrict__ att_d,
            int M, int K) {
    const float* A = Ain ? Ain : g_hn;   // layer 2 reads relu(h1)
    __shared__ float As[BK][BM];
    __shared__ float Bs[BK][BN];

    int tid = threadIdx.x;
    int tx  = tid & 15;    // 16 col groups of 8
    int ty  = tid >> 4;    // 8 row groups of 8
    int m0  = blockIdx.x * BM;

    float acc[8][8];
    #pragma unroll
    for (int i = 0; i < 8; i++)
        #pragma unroll
        for (int j = 0; j < 8; j++) acc[i][j] = 0.0f;

    for (int k0 = 0; k0 < K; k0 += BK) {
        // A tile 64x16 (256 float4), 2 per thread, stored transposed
        #pragma unroll
        for (int t = 0; t < 2; t++) {
            int q   = tid * 2 + t;
            int r   = q >> 2;          // row in tile 0..63
            int c4  = (q & 3) << 2;    // col 0,4,8,12
            int gm  = m0 + r;
            float4 av = (gm < M) ? *(const float4*)(A + (size_t)gm * K + k0 + c4)
                                 : make_float4(0.f, 0.f, 0.f, 0.f);
            As[c4 + 0][r] = av.x;
            As[c4 + 1][r] = av.y;
            As[c4 + 2][r] = av.z;
            As[c4 + 3][r] = av.w;
        }
        // B tile 16x128 (512 float4), 4 per thread
        #pragma unroll
        for (int t = 0; t < 4; t++) {
            int q = tid * 4 + t;
            int r = q >> 5;            // row 0..15
            int c = (q & 31) << 2;     // col
            *(float4*)&Bs[r][c] = *(const float4*)(B + (size_t)(k0 + r) * BN + c);
        }
        __syncthreads();

        #pragma unroll
        for (int kk = 0; kk < BK; kk++) {
            float4 a0 = *(const float4*)&As[kk][ty * 8];
            float4 a1 = *(const float4*)&As[kk][ty * 8 + 4];
            float4 b0 = *(const float4*)&Bs[kk][tx * 8];
            float4 b1 = *(const float4*)&Bs[kk][tx * 8 + 4];
            float a[8] = {a0.x, a0.y, a0.z, a0.w, a1.x, a1.y, a1.z, a1.w};
            float b[8] = {b0.x, b0.y, b0.z, b0.w, b1.x, b1.y, b1.z, b1.w};
            #pragma unroll
            for (int i = 0; i < 8; i++)
                #pragma unroll
                for (int j = 0; j < 8; j++)
                    acc[i][j] += a[i] * b[j];
        }
        __syncthreads();
    }

    // attention weights for this thread's 8 columns
    float asw[8], adw[8];
    #pragma unroll
    for (int j = 0; j < 8; j++) {
        asw[j] = att_s[tx * 8 + j];
        adw[j] = att_d[tx * 8 + j];
    }

    #pragma unroll
    for (int i = 0; i < 8; i++) {
        int gm = m0 + ty * 8 + i;
        float ps = 0.f, pd = 0.f;
        #pragma unroll
        for (int j = 0; j < 8; j++) {
            ps += acc[i][j] * asw[j];
            pd += acc[i][j] * adw[j];
        }
        // reduce over the 16 tx-threads (half-warp; lane = ((ty&1)<<4)|tx)
        #pragma unroll
        for (int o = 8; o; o >>= 1) {
            ps += __shfl_down_sync(0xffffffffu, ps, o, 16);
            pd += __shfl_down_sync(0xffffffffu, pd, o, 16);
        }
        if (gm < M) {
            *(float4*)(g_h + (size_t)gm * BN + tx * 8) =
                make_float4(acc[i][0], acc[i][1], acc[i][2], acc[i][3]);
            *(float4*)(g_h + (size_t)gm * BN + tx * 8 + 4) =
                make_float4(acc[i][4], acc[i][5], acc[i][6], acc[i][7]);
            if (tx == 0) { g_as[gm] = ps; g_ad[gm] = pd; }
        }
    }
}

// ---------------- aggregation: warp per dst node, float4, no atomics ---------
// out[n][:] = relu( (Σ_e w_e h[src_e]) / (Σ_e w_e) + bias ),
// w_e = exp(leaky_relu(a_s[src] + a_d[n]))   (segment-max skipped: exp(e)/Σexp(e))
template<bool TAIL>
__global__ void k_agg(const float* __restrict__ bias,
                      const float* __restrict__ Wr, const float* __restrict__ br,
                      const float* __restrict__ Wc) {
    int warp = threadIdx.x >> 5;
    int lane = threadIdx.x & 31;
    int n = blockIdx.x * 4 + warp;
    __shared__ float s0s[4], s1s[4];

    int s = g_off[n], e = g_off[n + 1];
    float ad = g_ad[n];
    const float4* h4 = (const float4*)g_h;
    float4 acc = make_float4(0.f, 0.f, 0.f, 0.f);
    float z = 0.f;

    int p = s;
    for (; p + 2 <= e; p += 2) {
        int a0 = __ldg(&g_psrc[p]);
        int a1 = __ldg(&g_psrc[p + 1]);
        float e0 = g_as[a0] + ad;
        float e1 = g_as[a1] + ad;
        e0 = e0 > 0.f ? e0 : NEG_SLOPE * e0;
        e1 = e1 > 0.f ? e1 : NEG_SLOPE * e1;
        float w0 = __expf(e0), w1 = __expf(e1);
        float4 h0 = h4[(size_t)a0 * 32 + lane];
        float4 h1 = h4[(size_t)a1 * 32 + lane];
        z += w0 + w1;
        acc.x += w0 * h0.x + w1 * h1.x;
        acc.y += w0 * h0.y + w1 * h1.y;
        acc.z += w0 * h0.z + w1 * h1.z;
        acc.w += w0 * h0.w + w1 * h1.w;
    }
    if (p < e) {
        int a0 = __ldg(&g_psrc[p]);
        float e0 = g_as[a0] + ad;
        e0 = e0 > 0.f ? e0 : NEG_SLOPE * e0;
        float w0 = __expf(e0);
        float4 h0 = h4[(size_t)a0 * 32 + lane];
        z += w0;
        acc.x += w0 * h0.x; acc.y += w0 * h0.y;
        acc.z += w0 * h0.z; acc.w += w0 * h0.w;
    }

    float inv = 1.0f / z;
    float4 b4 = ((const float4*)bias)[lane];
    float4 v;
    v.x = fmaxf(acc.x * inv + b4.x, 0.f);
    v.y = fmaxf(acc.y * inv + b4.y, 0.f);
    v.z = fmaxf(acc.z * inv + b4.z, 0.f);
    v.w = fmaxf(acc.w * inv + b4.w, 0.f);

    if (!TAIL) {
        ((float4*)g_hn)[(size_t)n * 32 + lane] = v;
    } else {
        // fused tail: r = v·Wr + br ; acc2 += r * Wc[n]
        float4 wr = ((const float4*)Wr)[lane];
        float dot = v.x * wr.x + v.y * wr.y + v.z * wr.z + v.w * wr.w;
        #pragma unroll
        for (int o = 16; o; o >>= 1) dot += __shfl_down_sync(0xffffffffu, dot, o);
        if (lane == 0) {
            float r = dot + br[0];
            s0s[warp] = r * Wc[n * 2 + 0];
            s1s[warp] = r * Wc[n * 2 + 1];
        }
        __syncthreads();
        if (threadIdx.x == 0) {
            atomicAdd(&g_acc2[0], s0s[0] + s0s[1] + s0s[2] + s0s[3]);
            atomicAdd(&g_acc2[1], s1s[0] + s1s[1] + s1s[2] + s1s[3]);
        }
    }
}

__global__ void k_fin(const float* __restrict__ bc, float* __restrict__ out) {
    int i = threadIdx.x;
    if (i < 2) out[i] = g_acc2[i] + bc[i];
}

// ---------------- launch -------------------------------------------------------
extern "C" void kernel_launch(void* const* d_in, const int* in_sizes, int n_in,
                              void* d_out, int out_size) {
    const float* x   = (const float*)d_in[0];
    const int*   ei  = (const int*)  d_in[1];
    const float* W1  = (const float*)d_in[2];
    const float* as1 = (const float*)d_in[3];
    const float* ad1 = (const float*)d_in[4];
    const float* b1  = (const float*)d_in[5];
    const float* W2  = (const float*)d_in[6];
    const float* as2 = (const float*)d_in[7];
    const float* ad2 = (const float*)d_in[8];
    const float* b2  = (const float*)d_in[9];
    const float* Wr  = (const float*)d_in[10];
    const float* br  = (const float*)d_in[11];
    const float* Wc  = (const float*)d_in[12];
    const float* bc  = (const float*)d_in[13];
    float* out = (float*)d_out;

    // CSR build
    k_init <<<(N_NODES + 255) / 256, 256>>>();
    k_hist <<<(ETOT + 255) / 256, 256>>>(ei);
    k_scan <<<1, 1024>>>();
    k_place<<<(ETOT + 255) / 256, 256>>>(ei);

    int gemm_grid = (N_NODES + BM - 1) / BM;

    // layer 1
    k_gemm<<<gemm_grid, 128>>>(x, W1, as1, ad1, N_NODES, F_IN);
    k_agg<false><<<N_NODES / 4, 128>>>(b1, nullptr, nullptr, nullptr);

    // layer 2 (+ fused tail)
    k_gemm<<<gemm_grid, 128>>>(nullptr, W2, as2, ad2, N_NODES, H);
    k_agg<true><<<N_NODES / 4, 128>>>(b2, Wr, br, Wc);

    k_fin<<<1, 32>>>(bc, out);
}